// round 14
// baseline (speedup 1.0000x reference)
#include <cuda_runtime.h>
#include <cuda_fp16.h>
#include <cstdint>

// Problem constants (fixed by the reference)
#define NN 100000
#define EE 3200000
#define DD 128
#define NNP 100096           // padded row count = 782*128 (rows >= NN stay zero)
#define NB_SCAN 98           // ceil(NN / 1024)

// ---------------- static device scratch ----------------
// RULE (rounds 3/5/6/7): g_* symbols referenced ONLY in device code.
__device__ int      g_cnt[NN];
__device__ int      g_rptr[NN + 1];
__device__ int      g_bsum[128];
// Packed edge: bits[0:17)=col (N < 2^17), bits[17:32)=fp16 val bits (sign=0, val in [0,1))
__device__ unsigned g_epack[EE];
// Z buffers, fp16. g_Zh[3] = fp16 X (written by xcast; read by hop0, GEMM seg0).
// hops: 3->0, 0->1, 1->2. GEMM segs read {3,0,1,2}.
__device__ __align__(16) __half g_Zh[4][(size_t)NNP * DD];
// W transposed to [seg][n][k], fp16
__device__ __align__(16) __half g_Wt[4 * DD * DD];

// ---------------- conversions (side stream, hidden under CSR build) ----------
__global__ void k_wcast(const float* __restrict__ W) {
    int idx = blockIdx.x * blockDim.x + threadIdx.x;   // [seg][n][k]
    if (idx >= 4 * DD * DD) return;
    int seg = idx >> 14;
    int rem = idx & 16383;
    int n = rem >> 7;
    int k = rem & 127;
    g_Wt[idx] = __float2half(W[(size_t)(seg * DD + k) * DD + n]);
}

__global__ void k_xcast(const float* __restrict__ X) {
    int idx = blockIdx.x * blockDim.x + threadIdx.x;   // half2 index
    if (idx >= NNP * (DD / 2)) return;
    int j = idx * 2;
    __half2 h;
    if (j < NN * DD) {
        float2 f = *(const float2*)&X[j];
        h = __float22half2_rn(f);
    } else {
        h = __float2half2_rn(0.f);
    }
    *(__half2*)&g_Zh[3][j] = h;
}

// ---------------- CSR build ----------------
__global__ void k_zero_cnt() {
    int i = blockIdx.x * blockDim.x + threadIdx.x;
    if (i < NN) g_cnt[i] = 0;
}

// Scalar hist (R12 evidence: faster than int4-vectorized; atomic-bound)
__global__ void k_hist(const int* __restrict__ row) {
    int e = blockIdx.x * blockDim.x + threadIdx.x;
    if (e < EE) atomicAdd(&g_cnt[row[e]], 1);
}

__global__ void k_scan1() {
    __shared__ int s[1024];
    int t = threadIdx.x;
    int i = blockIdx.x * 1024 + t;
    int v = (i < NN) ? g_cnt[i] : 0;
    s[t] = v;
    __syncthreads();
    for (int off = 1; off < 1024; off <<= 1) {
        int u = (t >= off) ? s[t - off] : 0;
        __syncthreads();
        s[t] += u;
        __syncthreads();
    }
    if (i < NN) g_rptr[i] = s[t] - v;
    if (t == 1023) g_bsum[blockIdx.x] = s[1023];
}

__global__ void k_scan2() {
    __shared__ int s[128];
    int t = threadIdx.x;
    int v = (t < NB_SCAN) ? g_bsum[t] : 0;
    s[t] = v;
    __syncthreads();
    for (int off = 1; off < 128; off <<= 1) {
        int u = (t >= off) ? s[t - off] : 0;
        __syncthreads();
        s[t] += u;
        __syncthreads();
    }
    g_bsum[t] = s[t] - v;
}

__global__ void k_scan3() {
    int i = blockIdx.x * blockDim.x + threadIdx.x;
    if (i < NN) {
        int p = g_rptr[i] + g_bsum[i >> 10];
        g_rptr[i] = p;
        g_cnt[i]  = p;
    }
    if (i == 0) g_rptr[NN] = EE;
}

// 4 edges per thread (EE % 4 == 0)
__global__ void k_scatter(const int* __restrict__ row, const int* __restrict__ col,
                          const float* __restrict__ val) {
    int e = (blockIdx.x * blockDim.x + threadIdx.x) * 4;
    if (e < EE) {
        int4   r = *(const int4*)&row[e];
        int4   c = *(const int4*)&col[e];
        float4 v = *(const float4*)&val[e];
        int p;
        unsigned hb;
        p = atomicAdd(&g_cnt[r.x], 1);
        hb = __half_as_ushort(__float2half_rn(v.x));
        g_epack[p] = (hb << 17) | (unsigned)c.x;
        p = atomicAdd(&g_cnt[r.y], 1);
        hb = __half_as_ushort(__float2half_rn(v.y));
        g_epack[p] = (hb << 17) | (unsigned)c.y;
        p = atomicAdd(&g_cnt[r.z], 1);
        hb = __half_as_ushort(__float2half_rn(v.z));
        g_epack[p] = (hb << 17) | (unsigned)c.z;
        p = atomicAdd(&g_cnt[r.w], 1);
        hb = __half_as_ushort(__float2half_rn(v.w));
        g_epack[p] = (hb << 17) | (unsigned)c.w;
    }
}

// ---------------- SpMM: warp per row (R12-proven, byte-identical) ------------
__global__ void __launch_bounds__(256) k_spmm(int srcIdx, int dstIdx) {
    const uint2* __restrict__ Zin  = (const uint2*)&g_Zh[srcIdx][0];
    uint2* __restrict__       Zout = (uint2*)&g_Zh[dstIdx][0];

    int w = (blockIdx.x * blockDim.x + threadIdx.x) >> 5;
    if (w >= NN) return;
    int lane = threadIdx.x & 31;

    int s = g_rptr[w], e = g_rptr[w + 1];
    float a0 = 0.f, a1 = 0.f, a2 = 0.f, a3 = 0.f;
    float b0 = 0.f, b1 = 0.f, b2 = 0.f, b3 = 0.f;
    int i = s;
    for (; i + 8 <= e; i += 8) {
        unsigned pk[8];
#pragma unroll
        for (int u = 0; u < 8; u++) pk[u] = g_epack[i + u];
        uint2 z[8];
#pragma unroll
        for (int u = 0; u < 8; u++)
            z[u] = Zin[(size_t)(pk[u] & 0x1FFFFu) * 32 + lane];
#pragma unroll
        for (int u = 0; u < 8; u++) {
            float v = __half2float(__ushort_as_half((unsigned short)(pk[u] >> 17)));
            float2 f0 = __half22float2(*(__half2*)&z[u].x);
            float2 f1 = __half22float2(*(__half2*)&z[u].y);
            if (u & 1) {
                b0 += v * f0.x; b1 += v * f0.y; b2 += v * f1.x; b3 += v * f1.y;
            } else {
                a0 += v * f0.x; a1 += v * f0.y; a2 += v * f1.x; a3 += v * f1.y;
            }
        }
    }
    for (; i < e; i++) {
        unsigned pk = g_epack[i];
        float v = __half2float(__ushort_as_half((unsigned short)(pk >> 17)));
        uint2 z = Zin[(size_t)(pk & 0x1FFFFu) * 32 + lane];
        float2 f0 = __half22float2(*(__half2*)&z.x);
        float2 f1 = __half22float2(*(__half2*)&z.y);
        a0 += v * f0.x; a1 += v * f0.y; a2 += v * f1.x; a3 += v * f1.y;
    }
    a0 += b0; a1 += b1; a2 += b2; a3 += b3;
    uint2 o;
    __half2 h0 = __float22half2_rn(make_float2(a0, a1));
    __half2 h1 = __float22half2_rn(make_float2(a2, a3));
    o.x = *(unsigned int*)&h0;
    o.y = *(unsigned int*)&h1;
    Zout[(size_t)w * 32 + lane] = o;
}

// ---------------- Tensor-core GEMM over NSEG segments (pipelined) ------------
// seg indices FIRST..FIRST+NSEG-1; H_seg read from g_Zh[(seg==0)?3:seg-1].
// RMW=false: out = acc + bias. RMW=true: out += acc.
#define KC 64
#define SAS 72
#define SBS 72

template <int FIRST, int NSEG, bool RMW>
__global__ void __launch_bounds__(256) k_gemm(const float* __restrict__ bias,
                                              float* __restrict__ out) {
    __shared__ __half sA[128 * SAS];
    __shared__ __half sB[128 * SBS];

    int tid  = threadIdx.x;
    int wid  = tid >> 5;
    int lane = tid & 31;
    int wm = wid & 1;          // row half: rows wm*64
    int wn = wid >> 1;         // col group: cols wn*32
    int rowBase = blockIdx.x * 128;

    int lr = lane >> 2;        // 0..7
    int lc = lane & 3;         // 0..3

    int strR[4], strK[4];
#pragma unroll
    for (int u = 0; u < 4; u++) {
        int idx = tid + u * 256;
        strR[u] = idx >> 3;
        strK[u] = (idx & 7) * 8;
    }

    float acc[4][4][4];
#pragma unroll
    for (int mi = 0; mi < 4; mi++)
#pragma unroll
        for (int ni = 0; ni < 4; ni++)
#pragma unroll
            for (int q = 0; q < 4; q++) acc[mi][ni][q] = 0.f;

    uint4 pa[4], pb[4];
    {
        const int seg0 = FIRST;
        const __half* __restrict__ zsrc = &g_Zh[(seg0 == 0) ? 3 : seg0 - 1][0];
        const __half* __restrict__ wsrc = &g_Wt[seg0 * DD * DD];
#pragma unroll
        for (int u = 0; u < 4; u++) {
            pa[u] = *(const uint4*)&zsrc[(size_t)(rowBase + strR[u]) * DD + strK[u]];
            pb[u] = *(const uint4*)&wsrc[strR[u] * DD + strK[u]];
        }
    }

    const int NST = 2 * NSEG;
    for (int st = 0; st < NST; st++) {
#pragma unroll
        for (int u = 0; u < 4; u++) {
            *(uint4*)&sA[strR[u] * SAS + strK[u]] = pa[u];
            *(uint4*)&sB[strR[u] * SBS + strK[u]] = pb[u];
        }
        __syncthreads();

        if (st < NST - 1) {
            int seg = FIRST + ((st + 1) >> 1);
            int kk  = ((st + 1) & 1) * KC;
            const __half* __restrict__ zsrc = &g_Zh[(seg == 0) ? 3 : seg - 1][0];
            const __half* __restrict__ wsrc = &g_Wt[seg * DD * DD];
#pragma unroll
            for (int u = 0; u < 4; u++) {
                pa[u] = *(const uint4*)&zsrc[(size_t)(rowBase + strR[u]) * DD + kk + strK[u]];
                pb[u] = *(const uint4*)&wsrc[strR[u] * DD + kk + strK[u]];
            }
        }

#pragma unroll
        for (int ks = 0; ks < KC / 16; ks++) {
            int k0 = ks * 16 + lc * 2;
            unsigned wb0[4], wb1[4];
#pragma unroll
            for (int ni = 0; ni < 4; ni++) {
                int n = wn * 32 + ni * 8 + lr;
                wb0[ni] = *(const unsigned*)&sB[n * SBS + k0];
                wb1[ni] = *(const unsigned*)&sB[n * SBS + k0 + 8];
            }
#pragma unroll
            for (int mi = 0; mi < 4; mi++) {
                int r = wm * 64 + mi * 16 + lr;
                unsigned a0 = *(const unsigned*)&sA[r * SAS + k0];
                unsigned a1 = *(const unsigned*)&sA[(r + 8) * SAS + k0];
                unsigned a2 = *(const unsigned*)&sA[r * SAS + k0 + 8];
                unsigned a3 = *(const unsigned*)&sA[(r + 8) * SAS + k0 + 8];
#pragma unroll
                for (int ni = 0; ni < 4; ni++) {
                    asm volatile(
                        "mma.sync.aligned.m16n8k16.row.col.f32.f16.f16.f32 "
                        "{%0,%1,%2,%3}, {%4,%5,%6,%7}, {%8,%9}, {%0,%1,%2,%3};"
                        : "+f"(acc[mi][ni][0]), "+f"(acc[mi][ni][1]),
                          "+f"(acc[mi][ni][2]), "+f"(acc[mi][ni][3])
                        : "r"(a0), "r"(a1), "r"(a2), "r"(a3),
                          "r"(wb0[ni]), "r"(wb1[ni]));
                }
            }
        }
        __syncthreads();
    }

    // Epilogue
#pragma unroll
    for (int ni = 0; ni < 4; ni++) {
        int col = wn * 32 + ni * 8 + lc * 2;
        float2 bb = make_float2(0.f, 0.f);
        if (!RMW) bb = *(const float2*)&bias[col];
#pragma unroll
        for (int mi = 0; mi < 4; mi++) {
            int r0 = rowBase + wm * 64 + mi * 16 + lr;
            if (r0 < NN) {
                float2 o0;
                if (RMW) {
                    o0 = *(float2*)&out[(size_t)r0 * DD + col];
                    o0.x += acc[mi][ni][0]; o0.y += acc[mi][ni][1];
                } else {
                    o0 = make_float2(acc[mi][ni][0] + bb.x, acc[mi][ni][1] + bb.y);
                }
                *(float2*)&out[(size_t)r0 * DD + col] = o0;
            }
            int r1 = r0 + 8;
            if (r1 < NN) {
                float2 o1;
                if (RMW) {
                    o1 = *(float2*)&out[(size_t)r1 * DD + col];
                    o1.x += acc[mi][ni][2]; o1.y += acc[mi][ni][3];
                } else {
                    o1 = make_float2(acc[mi][ni][2] + bb.x, acc[mi][ni][3] + bb.y);
                }
                *(float2*)&out[(size_t)r1 * DD + col] = o1;
            }
        }
    }
}

// ---------------- launch: no g_* symbols referenced in host code -------------
static cudaStream_t s_side = nullptr;
static cudaEvent_t s_evFork, s_evConv, s_evG0;

extern "C" void kernel_launch(void* const* d_in, const int* in_sizes, int n_in,
                              void* d_out, int out_size) {
    const float* X  = (const float*)d_in[0];
    const int*   Ar = (const int*)d_in[1];
    const int*   Ac = (const int*)d_in[2];
    const float* Av = (const float*)d_in[3];
    const float* W  = (const float*)d_in[4];
    const float* b  = (const float*)d_in[5];
    float* out = (float*)d_out;

    if (!s_side) {
        cudaStreamCreateWithFlags(&s_side, cudaStreamNonBlocking);
        cudaEventCreateWithFlags(&s_evFork, cudaEventDisableTiming);
        cudaEventCreateWithFlags(&s_evConv, cudaEventDisableTiming);
        cudaEventCreateWithFlags(&s_evG0, cudaEventDisableTiming);
    }

    // Side stream: conversions, then seg-0 GEMM (out = Xh@W0 + b), all hidden
    // under the atomic-bound CSR build on the main stream.
    cudaEventRecord(s_evFork, 0);
    cudaStreamWaitEvent(s_side, s_evFork, 0);
    k_wcast<<<(4 * DD * DD + 255) / 256, 256, 0, s_side>>>(W);
    k_xcast<<<(NNP * (DD / 2) + 255) / 256, 256, 0, s_side>>>(X);
    cudaEventRecord(s_evConv, s_side);
    k_gemm<0, 1, false><<<NNP / 128, 256, 0, s_side>>>(b, out);
    cudaEventRecord(s_evG0, s_side);

    // Main stream: CSR build
    k_zero_cnt<<<(NN + 255) / 256, 256>>>();
    k_hist<<<(EE + 255) / 256, 256>>>(Ar);
    k_scan1<<<NB_SCAN, 1024>>>();
    k_scan2<<<1, 128>>>();
    k_scan3<<<(NN + 255) / 256, 256>>>();
    k_scatter<<<(EE / 4 + 255) / 256, 256>>>(Ar, Ac, Av);

    // 3 SpMM hops (need Xh -> wait for conversions only, not the seg-0 GEMM)
    cudaStreamWaitEvent(0, s_evConv, 0);
    int spmm_blocks = (NN * 32 + 255) / 256;
    k_spmm<<<spmm_blocks, 256>>>(3, 0);   // Xh -> Z1
    k_spmm<<<spmm_blocks, 256>>>(0, 1);   // Z1 -> Z2
    k_spmm<<<spmm_blocks, 256>>>(1, 2);   // Z2 -> Z3

    // Tail: 3-segment GEMM (Z1,Z2,Z3), RMW into out (seg-0 result + bias).
    cudaStreamWaitEvent(0, s_evG0, 0);
    k_gemm<1, 3, true><<<NNP / 128, 256>>>(b, out);
}

// round 15
// speedup vs baseline: 1.1163x; 1.1163x over previous
#include <cuda_runtime.h>
#include <cuda_fp16.h>
#include <cstdint>

// Problem constants (fixed by the reference)
#define NN 100000
#define EE 3200000
#define DD 128
#define NNP 100096           // padded row count = 782*128 (rows >= NN stay zero)
#define NB_SCAN 98           // ceil(NN / 1024)

// ---------------- static device scratch ----------------
// RULE (rounds 3/5/6/7): g_* symbols referenced ONLY in device code.
__device__ int      g_cnt[NN];
__device__ int      g_rptr[NN + 1];
__device__ int      g_bsum[128];
// Packed edge: bits[0:17)=col (N < 2^17), bits[17:32)=fp16 val bits (sign=0, val in [0,1))
__device__ unsigned g_epack[EE];
// Z buffers, fp16. g_Zh[3] = fp16 X (written by xcast, read by hop0 and GEMM seg0).
// hops: 3->0, 0->1, 1->2. GEMM segs read {3,0,1,2}.
__device__ __align__(16) __half g_Zh[4][(size_t)NNP * DD];
// W transposed to [seg][n][k], fp16
__device__ __align__(16) __half g_Wt[4 * DD * DD];

// ---------------- conversions (side stream, hidden under CSR build) ----------
__global__ void k_wcast(const float* __restrict__ W) {
    int idx = blockIdx.x * blockDim.x + threadIdx.x;   // [seg][n][k]
    if (idx >= 4 * DD * DD) return;
    int seg = idx >> 14;
    int rem = idx & 16383;
    int n = rem >> 7;
    int k = rem & 127;
    g_Wt[idx] = __float2half(W[(size_t)(seg * DD + k) * DD + n]);
}

__global__ void k_xcast(const float* __restrict__ X) {
    int idx = blockIdx.x * blockDim.x + threadIdx.x;   // half2 index
    if (idx >= NNP * (DD / 2)) return;
    int j = idx * 2;
    __half2 h;
    if (j < NN * DD) {
        float2 f = *(const float2*)&X[j];
        h = __float22half2_rn(f);
    } else {
        h = __float2half2_rn(0.f);
    }
    *(__half2*)&g_Zh[3][j] = h;
}

// ---------------- CSR build ----------------
__global__ void k_zero_cnt() {
    int i = blockIdx.x * blockDim.x + threadIdx.x;
    if (i < NN) g_cnt[i] = 0;
}

// Scalar hist (measured: 22.3us scalar vs 25.4us int4-vectorized; atomic-bound)
__global__ void k_hist(const int* __restrict__ row) {
    int e = blockIdx.x * blockDim.x + threadIdx.x;
    if (e < EE) atomicAdd(&g_cnt[row[e]], 1);
}

__global__ void k_scan1() {
    __shared__ int s[1024];
    int t = threadIdx.x;
    int i = blockIdx.x * 1024 + t;
    int v = (i < NN) ? g_cnt[i] : 0;
    s[t] = v;
    __syncthreads();
    for (int off = 1; off < 1024; off <<= 1) {
        int u = (t >= off) ? s[t - off] : 0;
        __syncthreads();
        s[t] += u;
        __syncthreads();
    }
    if (i < NN) g_rptr[i] = s[t] - v;
    if (t == 1023) g_bsum[blockIdx.x] = s[1023];
}

__global__ void k_scan2() {
    __shared__ int s[128];
    int t = threadIdx.x;
    int v = (t < NB_SCAN) ? g_bsum[t] : 0;
    s[t] = v;
    __syncthreads();
    for (int off = 1; off < 128; off <<= 1) {
        int u = (t >= off) ? s[t - off] : 0;
        __syncthreads();
        s[t] += u;
        __syncthreads();
    }
    g_bsum[t] = s[t] - v;
}

__global__ void k_scan3() {
    int i = blockIdx.x * blockDim.x + threadIdx.x;
    if (i < NN) {
        int p = g_rptr[i] + g_bsum[i >> 10];
        g_rptr[i] = p;
        g_cnt[i]  = p;
    }
    if (i == 0) g_rptr[NN] = EE;
}

// 4 edges per thread (EE % 4 == 0)
__global__ void k_scatter(const int* __restrict__ row, const int* __restrict__ col,
                          const float* __restrict__ val) {
    int e = (blockIdx.x * blockDim.x + threadIdx.x) * 4;
    if (e < EE) {
        int4   r = *(const int4*)&row[e];
        int4   c = *(const int4*)&col[e];
        float4 v = *(const float4*)&val[e];
        int p;
        unsigned hb;
        p = atomicAdd(&g_cnt[r.x], 1);
        hb = __half_as_ushort(__float2half_rn(v.x));
        g_epack[p] = (hb << 17) | (unsigned)c.x;
        p = atomicAdd(&g_cnt[r.y], 1);
        hb = __half_as_ushort(__float2half_rn(v.y));
        g_epack[p] = (hb << 17) | (unsigned)c.y;
        p = atomicAdd(&g_cnt[r.z], 1);
        hb = __half_as_ushort(__float2half_rn(v.z));
        g_epack[p] = (hb << 17) | (unsigned)c.z;
        p = atomicAdd(&g_cnt[r.w], 1);
        hb = __half_as_ushort(__float2half_rn(v.w));
        g_epack[p] = (hb << 17) | (unsigned)c.w;
    }
}

// ---------------- SpMM: warp per row (R12-proven, byte-identical) ------------
__global__ void __launch_bounds__(256) k_spmm(int srcIdx, int dstIdx) {
    const uint2* __restrict__ Zin  = (const uint2*)&g_Zh[srcIdx][0];
    uint2* __restrict__       Zout = (uint2*)&g_Zh[dstIdx][0];

    int w = (blockIdx.x * blockDim.x + threadIdx.x) >> 5;
    if (w >= NN) return;
    int lane = threadIdx.x & 31;

    int s = g_rptr[w], e = g_rptr[w + 1];
    float a0 = 0.f, a1 = 0.f, a2 = 0.f, a3 = 0.f;
    float b0 = 0.f, b1 = 0.f, b2 = 0.f, b3 = 0.f;
    int i = s;
    for (; i + 8 <= e; i += 8) {
        unsigned pk[8];
#pragma unroll
        for (int u = 0; u < 8; u++) pk[u] = g_epack[i + u];
        uint2 z[8];
#pragma unroll
        for (int u = 0; u < 8; u++)
            z[u] = Zin[(size_t)(pk[u] & 0x1FFFFu) * 32 + lane];
#pragma unroll
        for (int u = 0; u < 8; u++) {
            float v = __half2float(__ushort_as_half((unsigned short)(pk[u] >> 17)));
            float2 f0 = __half22float2(*(__half2*)&z[u].x);
            float2 f1 = __half22float2(*(__half2*)&z[u].y);
            if (u & 1) {
                b0 += v * f0.x; b1 += v * f0.y; b2 += v * f1.x; b3 += v * f1.y;
            } else {
                a0 += v * f0.x; a1 += v * f0.y; a2 += v * f1.x; a3 += v * f1.y;
            }
        }
    }
    for (; i < e; i++) {
        unsigned pk = g_epack[i];
        float v = __half2float(__ushort_as_half((unsigned short)(pk >> 17)));
        uint2 z = Zin[(size_t)(pk & 0x1FFFFu) * 32 + lane];
        float2 f0 = __half22float2(*(__half2*)&z.x);
        float2 f1 = __half22float2(*(__half2*)&z.y);
        a0 += v * f0.x; a1 += v * f0.y; a2 += v * f1.x; a3 += v * f1.y;
    }
    a0 += b0; a1 += b1; a2 += b2; a3 += b3;
    uint2 o;
    __half2 h0 = __float22half2_rn(make_float2(a0, a1));
    __half2 h1 = __float22half2_rn(make_float2(a2, a3));
    o.x = *(unsigned int*)&h0;
    o.y = *(unsigned int*)&h1;
    Zout[(size_t)w * 32 + lane] = o;
}

// ---------------- Fused 4-seg tensor-core GEMM, reg-prefetch pipeline --------
// 8 stages (seg 0..3 x kk in {0,64}); stage st+1's tiles prefetched into
// registers while stage st's HMMAs run on smem. (R13-proven)
#define KC 64
#define SAS 72
#define SBS 72

__global__ void __launch_bounds__(256) k_gemm(const float* __restrict__ bias,
                                              float* __restrict__ out) {
    __shared__ __half sA[128 * SAS];
    __shared__ __half sB[128 * SBS];

    const int SEGBUF[4] = {3, 0, 1, 2};

    int tid  = threadIdx.x;
    int wid  = tid >> 5;
    int lane = tid & 31;
    int wm = wid & 1;          // row half: rows wm*64
    int wn = wid >> 1;         // col group: cols wn*32
    int rowBase = blockIdx.x * 128;

    int lr = lane >> 2;        // 0..7
    int lc = lane & 3;         // 0..3

    int strR[4], strK[4];
#pragma unroll
    for (int u = 0; u < 4; u++) {
        int idx = tid + u * 256;
        strR[u] = idx >> 3;           // 0..127
        strK[u] = (idx & 7) * 8;      // 0..56 step 8
    }

    float acc[4][4][4];
#pragma unroll
    for (int mi = 0; mi < 4; mi++)
#pragma unroll
        for (int ni = 0; ni < 4; ni++)
#pragma unroll
            for (int q = 0; q < 4; q++) acc[mi][ni][q] = 0.f;

    uint4 pa[4], pb[4];
    {
        const __half* __restrict__ zsrc = &g_Zh[SEGBUF[0]][0];
        const __half* __restrict__ wsrc = &g_Wt[0];
#pragma unroll
        for (int u = 0; u < 4; u++) {
            pa[u] = *(const uint4*)&zsrc[(size_t)(rowBase + strR[u]) * DD + strK[u]];
            pb[u] = *(const uint4*)&wsrc[strR[u] * DD + strK[u]];
        }
    }

    for (int st = 0; st < 8; st++) {
#pragma unroll
        for (int u = 0; u < 4; u++) {
            *(uint4*)&sA[strR[u] * SAS + strK[u]] = pa[u];
            *(uint4*)&sB[strR[u] * SBS + strK[u]] = pb[u];
        }
        __syncthreads();

        if (st < 7) {
            int seg = (st + 1) >> 1;
            int kk  = ((st + 1) & 1) * KC;
            const __half* __restrict__ zsrc = &g_Zh[SEGBUF[seg]][0];
            const __half* __restrict__ wsrc = &g_Wt[seg * DD * DD];
#pragma unroll
            for (int u = 0; u < 4; u++) {
                pa[u] = *(const uint4*)&zsrc[(size_t)(rowBase + strR[u]) * DD + kk + strK[u]];
                pb[u] = *(const uint4*)&wsrc[strR[u] * DD + kk + strK[u]];
            }
        }

#pragma unroll
        for (int ks = 0; ks < KC / 16; ks++) {
            int k0 = ks * 16 + lc * 2;
            unsigned wb0[4], wb1[4];
#pragma unroll
            for (int ni = 0; ni < 4; ni++) {
                int n = wn * 32 + ni * 8 + lr;
                wb0[ni] = *(const unsigned*)&sB[n * SBS + k0];
                wb1[ni] = *(const unsigned*)&sB[n * SBS + k0 + 8];
            }
#pragma unroll
            for (int mi = 0; mi < 4; mi++) {
                int r = wm * 64 + mi * 16 + lr;
                unsigned a0 = *(const unsigned*)&sA[r * SAS + k0];
                unsigned a1 = *(const unsigned*)&sA[(r + 8) * SAS + k0];
                unsigned a2 = *(const unsigned*)&sA[r * SAS + k0 + 8];
                unsigned a3 = *(const unsigned*)&sA[(r + 8) * SAS + k0 + 8];
#pragma unroll
                for (int ni = 0; ni < 4; ni++) {
                    asm volatile(
                        "mma.sync.aligned.m16n8k16.row.col.f32.f16.f16.f32 "
                        "{%0,%1,%2,%3}, {%4,%5,%6,%7}, {%8,%9}, {%0,%1,%2,%3};"
                        : "+f"(acc[mi][ni][0]), "+f"(acc[mi][ni][1]),
                          "+f"(acc[mi][ni][2]), "+f"(acc[mi][ni][3])
                        : "r"(a0), "r"(a1), "r"(a2), "r"(a3),
                          "r"(wb0[ni]), "r"(wb1[ni]));
                }
            }
        }
        __syncthreads();
    }

    // Epilogue: add bias, store fp32.
#pragma unroll
    for (int ni = 0; ni < 4; ni++) {
        int col = wn * 32 + ni * 8 + lc * 2;
        float2 bb = *(const float2*)&bias[col];
#pragma unroll
        for (int mi = 0; mi < 4; mi++) {
            int r0 = rowBase + wm * 64 + mi * 16 + lr;
            if (r0 < NN) {
                float2 o0 = make_float2(acc[mi][ni][0] + bb.x, acc[mi][ni][1] + bb.y);
                *(float2*)&out[(size_t)r0 * DD + col] = o0;
            }
            int r1 = r0 + 8;
            if (r1 < NN) {
                float2 o1 = make_float2(acc[mi][ni][2] + bb.x, acc[mi][ni][3] + bb.y);
                *(float2*)&out[(size_t)r1 * DD + col] = o1;
            }
        }
    }
}

// ---------------- launch: no g_* symbols referenced in host code -------------
static cudaStream_t s_side = nullptr;
static cudaEvent_t s_evFork, s_evConv;

extern "C" void kernel_launch(void* const* d_in, const int* in_sizes, int n_in,
                              void* d_out, int out_size) {
    const float* X  = (const float*)d_in[0];
    const int*   Ar = (const int*)d_in[1];
    const int*   Ac = (const int*)d_in[2];
    const float* Av = (const float*)d_in[3];
    const float* W  = (const float*)d_in[4];
    const float* b  = (const float*)d_in[5];
    float* out = (float*)d_out;

    if (!s_side) {
        cudaStreamCreateWithFlags(&s_side, cudaStreamNonBlocking);
        cudaEventCreateWithFlags(&s_evFork, cudaEventDisableTiming);
        cudaEventCreateWithFlags(&s_evConv, cudaEventDisableTiming);
    }

    // Side stream: fp16 conversions only (tiny, bandwidth-light), hidden
    // under the CSR build. No compute overlap (regressed in R9/R14).
    cudaEventRecord(s_evFork, 0);
    cudaStreamWaitEvent(s_side, s_evFork, 0);
    k_wcast<<<(4 * DD * DD + 255) / 256, 256, 0, s_side>>>(W);
    k_xcast<<<(NNP * (DD / 2) + 255) / 256, 256, 0, s_side>>>(X);
    cudaEventRecord(s_evConv, s_side);

    // Main stream: CSR build (scalar hist, vectorized scatter)
    k_zero_cnt<<<(NN + 255) / 256, 256>>>();
    k_hist<<<(EE + 255) / 256, 256>>>(Ar);
    k_scan1<<<NB_SCAN, 1024>>>();
    k_scan2<<<1, 128>>>();
    k_scan3<<<(NN + 255) / 256, 256>>>();
    k_scatter<<<(EE / 4 + 255) / 256, 256>>>(Ar, Ac, Av);

    // 3 SpMM hops (join conversions first; indices resolved device-side)
    cudaStreamWaitEvent(0, s_evConv, 0);
    int spmm_blocks = (NN * 32 + 255) / 256;
    k_spmm<<<spmm_blocks, 256>>>(3, 0);   // Xh -> Z1
    k_spmm<<<spmm_blocks, 256>>>(0, 1);   // Z1 -> Z2
    k_spmm<<<spmm_blocks, 256>>>(1, 2);   // Z2 -> Z3

    // Fused 4-segment tensor-core GEMM + bias (single kernel, pipelined)
    k_gemm<<<NNP / 128, 256>>>(b, out);
}

// round 16
// speedup vs baseline: 1.1210x; 1.0043x over previous
#include <cuda_runtime.h>
#include <cuda_fp16.h>
#include <cstdint>

// Problem constants (fixed by the reference)
#define NN 100000
#define EE 3200000
#define DD 128
#define NNP 100096           // padded row count = 782*128 (rows >= NN stay zero)
#define NB_SCAN 98           // ceil(NN / 1024)

// ---------------- static device scratch ----------------
// RULE (rounds 3/5/6/7): g_* symbols referenced ONLY in device code.
__device__ int      g_cnt[NN];
__device__ int      g_rptr[NN + 1];
__device__ int      g_bsum[128];
// Packed edge: bits[0:17)=col (N < 2^17), bits[17:32)=fp16 val bits (sign=0, val in [0,1))
__device__ unsigned g_epack[EE];
// Z buffers, fp16. g_Zh[3] = fp16 X (written by xcast, read by hop0 and GEMM seg0).
// hops: 3->0, 0->1, 1->2. GEMM segs read {3,0,1,2}.
__device__ __align__(16) __half g_Zh[4][(size_t)NNP * DD];
// W transposed to [seg][n][k], fp16
__device__ __align__(16) __half g_Wt[4 * DD * DD];

// ---------------- conversions (side stream, hidden under CSR build) ----------
__global__ void k_wcast(const float* __restrict__ W) {
    int idx = blockIdx.x * blockDim.x + threadIdx.x;   // [seg][n][k]
    if (idx >= 4 * DD * DD) return;
    int seg = idx >> 14;
    int rem = idx & 16383;
    int n = rem >> 7;
    int k = rem & 127;
    g_Wt[idx] = __float2half(W[(size_t)(seg * DD + k) * DD + n]);
}

__global__ void k_xcast(const float* __restrict__ X) {
    int idx = blockIdx.x * blockDim.x + threadIdx.x;   // half2 index
    if (idx >= NNP * (DD / 2)) return;
    int j = idx * 2;
    __half2 h;
    if (j < NN * DD) {
        float2 f = *(const float2*)&X[j];
        h = __float22half2_rn(f);
    } else {
        h = __float2half2_rn(0.f);
    }
    *(__half2*)&g_Zh[3][j] = h;
}

// ---------------- CSR build ----------------
__global__ void k_zero_cnt() {
    int i = blockIdx.x * blockDim.x + threadIdx.x;
    if (i < NN) g_cnt[i] = 0;
}

// Scalar hist (measured: 22.0us scalar vs 25.4us int4-vectorized; atomic-bound)
__global__ void k_hist(const int* __restrict__ row) {
    int e = blockIdx.x * blockDim.x + threadIdx.x;
    if (e < EE) atomicAdd(&g_cnt[row[e]], 1);
}

// Per-1024-chunk exclusive scan; emits raw chunk totals to g_bsum.
__global__ void k_scan1() {
    __shared__ int s[1024];
    int t = threadIdx.x;
    int i = blockIdx.x * 1024 + t;
    int v = (i < NN) ? g_cnt[i] : 0;
    s[t] = v;
    __syncthreads();
    for (int off = 1; off < 1024; off <<= 1) {
        int u = (t >= off) ? s[t - off] : 0;
        __syncthreads();
        s[t] += u;
        __syncthreads();
    }
    if (i < NN) g_rptr[i] = s[t] - v;
    if (t == 1023) g_bsum[blockIdx.x] = s[1023];
}

// Merged scan2+scan3: each 256-thread block lies in one 1024-chunk; it reduces
// its own chunk-prefix from g_bsum (<=98 values) then applies the offset.
__global__ void k_scan3() {
    __shared__ int s[128];
    int t = threadIdx.x;
    int base = blockIdx.x * 256;
    int sb = base >> 10;                 // this block's chunk index (constant)
    s[t & 127] = 0;
    __syncthreads();
    if (t < 128) s[t] = (t < sb && t < NB_SCAN) ? g_bsum[t] : 0;
    __syncthreads();
#pragma unroll
    for (int off = 64; off > 0; off >>= 1) {
        if (t < off) s[t] += s[t + off];
        __syncthreads();
    }
    int offset = s[0];
    int i = base + t;
    if (i < NN) {
        int p = g_rptr[i] + offset;
        g_rptr[i] = p;
        g_cnt[i]  = p;
    }
    if (i == 0) g_rptr[NN] = EE;
}

// 4 edges per thread (EE % 4 == 0)
__global__ void k_scatter(const int* __restrict__ row, const int* __restrict__ col,
                          const float* __restrict__ val) {
    int e = (blockIdx.x * blockDim.x + threadIdx.x) * 4;
    if (e < EE) {
        int4   r = *(const int4*)&row[e];
        int4   c = *(const int4*)&col[e];
        float4 v = *(const float4*)&val[e];
        int p;
        unsigned hb;
        p = atomicAdd(&g_cnt[r.x], 1);
        hb = __half_as_ushort(__float2half_rn(v.x));
        g_epack[p] = (hb << 17) | (unsigned)c.x;
        p = atomicAdd(&g_cnt[r.y], 1);
        hb = __half_as_ushort(__float2half_rn(v.y));
        g_epack[p] = (hb << 17) | (unsigned)c.y;
        p = atomicAdd(&g_cnt[r.z], 1);
        hb = __half_as_ushort(__float2half_rn(v.z));
        g_epack[p] = (hb << 17) | (unsigned)c.z;
        p = atomicAdd(&g_cnt[r.w], 1);
        hb = __half_as_ushort(__float2half_rn(v.w));
        g_epack[p] = (hb << 17) | (unsigned)c.w;
    }
}

// ---------------- SpMM: warp per row; __ldcg Z gathers (L1 kept for epack) ---
__global__ void __launch_bounds__(256) k_spmm(int srcIdx, int dstIdx) {
    const uint2* __restrict__ Zin  = (const uint2*)&g_Zh[srcIdx][0];
    uint2* __restrict__       Zout = (uint2*)&g_Zh[dstIdx][0];

    int w = (blockIdx.x * blockDim.x + threadIdx.x) >> 5;
    if (w >= NN) return;
    int lane = threadIdx.x & 31;

    int s = g_rptr[w], e = g_rptr[w + 1];
    float a0 = 0.f, a1 = 0.f, a2 = 0.f, a3 = 0.f;
    float b0 = 0.f, b1 = 0.f, b2 = 0.f, b3 = 0.f;
    int i = s;
    for (; i + 8 <= e; i += 8) {
        unsigned pk[8];
#pragma unroll
        for (int u = 0; u < 8; u++) pk[u] = g_epack[i + u];
        uint2 z[8];
#pragma unroll
        for (int u = 0; u < 8; u++)
            z[u] = __ldcg(&Zin[(size_t)(pk[u] & 0x1FFFFu) * 32 + lane]);
#pragma unroll
        for (int u = 0; u < 8; u++) {
            float v = __half2float(__ushort_as_half((unsigned short)(pk[u] >> 17)));
            float2 f0 = __half22float2(*(__half2*)&z[u].x);
            float2 f1 = __half22float2(*(__half2*)&z[u].y);
            if (u & 1) {
                b0 += v * f0.x; b1 += v * f0.y; b2 += v * f1.x; b3 += v * f1.y;
            } else {
                a0 += v * f0.x; a1 += v * f0.y; a2 += v * f1.x; a3 += v * f1.y;
            }
        }
    }
    for (; i < e; i++) {
        unsigned pk = g_epack[i];
        float v = __half2float(__ushort_as_half((unsigned short)(pk >> 17)));
        uint2 z = __ldcg(&Zin[(size_t)(pk & 0x1FFFFu) * 32 + lane]);
        float2 f0 = __half22float2(*(__half2*)&z.x);
        float2 f1 = __half22float2(*(__half2*)&z.y);
        a0 += v * f0.x; a1 += v * f0.y; a2 += v * f1.x; a3 += v * f1.y;
    }
    a0 += b0; a1 += b1; a2 += b2; a3 += b3;
    uint2 o;
    __half2 h0 = __float22half2_rn(make_float2(a0, a1));
    __half2 h1 = __float22half2_rn(make_float2(a2, a3));
    o.x = *(unsigned int*)&h0;
    o.y = *(unsigned int*)&h1;
    Zout[(size_t)w * 32 + lane] = o;
}

// ---------------- Fused 4-seg tensor-core GEMM, reg-prefetch pipeline --------
// (R13-proven, byte-identical)
#define KC 64
#define SAS 72
#define SBS 72

__global__ void __launch_bounds__(256) k_gemm(const float* __restrict__ bias,
                                              float* __restrict__ out) {
    __shared__ __half sA[128 * SAS];
    __shared__ __half sB[128 * SBS];

    const int SEGBUF[4] = {3, 0, 1, 2};

    int tid  = threadIdx.x;
    int wid  = tid >> 5;
    int lane = tid & 31;
    int wm = wid & 1;
    int wn = wid >> 1;
    int rowBase = blockIdx.x * 128;

    int lr = lane >> 2;
    int lc = lane & 3;

    int strR[4], strK[4];
#pragma unroll
    for (int u = 0; u < 4; u++) {
        int idx = tid + u * 256;
        strR[u] = idx >> 3;
        strK[u] = (idx & 7) * 8;
    }

    float acc[4][4][4];
#pragma unroll
    for (int mi = 0; mi < 4; mi++)
#pragma unroll
        for (int ni = 0; ni < 4; ni++)
#pragma unroll
            for (int q = 0; q < 4; q++) acc[mi][ni][q] = 0.f;

    uint4 pa[4], pb[4];
    {
        const __half* __restrict__ zsrc = &g_Zh[SEGBUF[0]][0];
        const __half* __restrict__ wsrc = &g_Wt[0];
#pragma unroll
        for (int u = 0; u < 4; u++) {
            pa[u] = *(const uint4*)&zsrc[(size_t)(rowBase + strR[u]) * DD + strK[u]];
            pb[u] = *(const uint4*)&wsrc[strR[u] * DD + strK[u]];
        }
    }

    for (int st = 0; st < 8; st++) {
#pragma unroll
        for (int u = 0; u < 4; u++) {
            *(uint4*)&sA[strR[u] * SAS + strK[u]] = pa[u];
            *(uint4*)&sB[strR[u] * SBS + strK[u]] = pb[u];
        }
        __syncthreads();

        if (st < 7) {
            int seg = (st + 1) >> 1;
            int kk  = ((st + 1) & 1) * KC;
            const __half* __restrict__ zsrc = &g_Zh[SEGBUF[seg]][0];
            const __half* __restrict__ wsrc = &g_Wt[seg * DD * DD];
#pragma unroll
            for (int u = 0; u < 4; u++) {
                pa[u] = *(const uint4*)&zsrc[(size_t)(rowBase + strR[u]) * DD + kk + strK[u]];
                pb[u] = *(const uint4*)&wsrc[strR[u] * DD + kk + strK[u]];
            }
        }

#pragma unroll
        for (int ks = 0; ks < KC / 16; ks++) {
            int k0 = ks * 16 + lc * 2;
            unsigned wb0[4], wb1[4];
#pragma unroll
            for (int ni = 0; ni < 4; ni++) {
                int n = wn * 32 + ni * 8 + lr;
                wb0[ni] = *(const unsigned*)&sB[n * SBS + k0];
                wb1[ni] = *(const unsigned*)&sB[n * SBS + k0 + 8];
            }
#pragma unroll
            for (int mi = 0; mi < 4; mi++) {
                int r = wm * 64 + mi * 16 + lr;
                unsigned a0 = *(const unsigned*)&sA[r * SAS + k0];
                unsigned a1 = *(const unsigned*)&sA[(r + 8) * SAS + k0];
                unsigned a2 = *(const unsigned*)&sA[r * SAS + k0 + 8];
                unsigned a3 = *(const unsigned*)&sA[(r + 8) * SAS + k0 + 8];
#pragma unroll
                for (int ni = 0; ni < 4; ni++) {
                    asm volatile(
                        "mma.sync.aligned.m16n8k16.row.col.f32.f16.f16.f32 "
                        "{%0,%1,%2,%3}, {%4,%5,%6,%7}, {%8,%9}, {%0,%1,%2,%3};"
                        : "+f"(acc[mi][ni][0]), "+f"(acc[mi][ni][1]),
                          "+f"(acc[mi][ni][2]), "+f"(acc[mi][ni][3])
                        : "r"(a0), "r"(a1), "r"(a2), "r"(a3),
                          "r"(wb0[ni]), "r"(wb1[ni]));
                }
            }
        }
        __syncthreads();
    }

    // Epilogue: add bias, store fp32.
#pragma unroll
    for (int ni = 0; ni < 4; ni++) {
        int col = wn * 32 + ni * 8 + lc * 2;
        float2 bb = *(const float2*)&bias[col];
#pragma unroll
        for (int mi = 0; mi < 4; mi++) {
            int r0 = rowBase + wm * 64 + mi * 16 + lr;
            if (r0 < NN) {
                float2 o0 = make_float2(acc[mi][ni][0] + bb.x, acc[mi][ni][1] + bb.y);
                *(float2*)&out[(size_t)r0 * DD + col] = o0;
            }
            int r1 = r0 + 8;
            if (r1 < NN) {
                float2 o1 = make_float2(acc[mi][ni][2] + bb.x, acc[mi][ni][3] + bb.y);
                *(float2*)&out[(size_t)r1 * DD + col] = o1;
            }
        }
    }
}

// ---------------- launch: no g_* symbols referenced in host code -------------
static cudaStream_t s_side = nullptr;
static cudaEvent_t s_evFork, s_evConv;

extern "C" void kernel_launch(void* const* d_in, const int* in_sizes, int n_in,
                              void* d_out, int out_size) {
    const float* X  = (const float*)d_in[0];
    const int*   Ar = (const int*)d_in[1];
    const int*   Ac = (const int*)d_in[2];
    const float* Av = (const float*)d_in[3];
    const float* W  = (const float*)d_in[4];
    const float* b  = (const float*)d_in[5];
    float* out = (float*)d_out;

    if (!s_side) {
        cudaStreamCreateWithFlags(&s_side, cudaStreamNonBlocking);
        cudaEventCreateWithFlags(&s_evFork, cudaEventDisableTiming);
        cudaEventCreateWithFlags(&s_evConv, cudaEventDisableTiming);
    }

    // Side stream: fp16 conversions only (bandwidth-light), hidden under the
    // CSR build. No compute overlap (regressed in R9/R14).
    cudaEventRecord(s_evFork, 0);
    cudaStreamWaitEvent(s_side, s_evFork, 0);
    k_wcast<<<(4 * DD * DD + 255) / 256, 256, 0, s_side>>>(W);
    k_xcast<<<(NNP * (DD / 2) + 255) / 256, 256, 0, s_side>>>(X);
    cudaEventRecord(s_evConv, s_side);

    // Main stream: CSR build (scalar hist, merged scan, vectorized scatter)
    k_zero_cnt<<<(NN + 255) / 256, 256>>>();
    k_hist<<<(EE + 255) / 256, 256>>>(Ar);
    k_scan1<<<NB_SCAN, 1024>>>();
    k_scan3<<<(NN + 255) / 256, 256>>>();
    k_scatter<<<(EE / 4 + 255) / 256, 256>>>(Ar, Ac, Av);

    // 3 SpMM hops (join conversions first; indices resolved device-side)
    cudaStreamWaitEvent(0, s_evConv, 0);
    int spmm_blocks = (NN * 32 + 255) / 256;
    k_spmm<<<spmm_blocks, 256>>>(3, 0);   // Xh -> Z1
    k_spmm<<<spmm_blocks, 256>>>(0, 1);   // Z1 -> Z2
    k_spmm<<<spmm_blocks, 256>>>(1, 2);   // Z2 -> Z3

    // Fused 4-segment tensor-core GEMM + bias (single kernel, pipelined)
    k_gemm<<<NNP / 128, 256>>>(b, out);
}